// round 15
// baseline (speedup 1.0000x reference)
#include <cuda_runtime.h>
#include <cuda_bf16.h>
#include <cuda_fp16.h>
#include <math.h>
#include <stdint.h>

#define B_ 32
#define T_ 63
#define NB 64
#define H_ 64
#define KIN 4096
#define BT (B_*T_)            // 2016
#define MROWS (BT*NB)         // 129024
#define NG 9
#define NCOLS (NG*H_)         // 576
#define KST 256               // [h(t-1); h; h(t+1); h(n-1)] x 64 (U hoisted to PCONST)

__device__ float d_h0[MROWS*H_];                     // input projection output (fp32)
__device__ float d_c[2][MROWS*H_];                   // cell state ping-pong
__device__ __half d_pre[(size_t)MROWS*NCOLS];        // gate pre-activations (fp16)
__device__ __half d_pcst[(size_t)MROWS*NCOLS];       // constant part: h0@U + gtt + b + gst (fp16)
__device__ float d_gt[B_*NB*H_];
__device__ float d_gs[BT*H_];
__device__ float d_gtt[NG*B_*NB*H_];
__device__ float d_gst[NG*BT*H_];
__device__ float d_gb2[NG*B_*NB*H_];                 // gtt + bias
__device__ __nv_bfloat16 d_Ah[2048*KIN], d_Al[2048*KIN];
__device__ __nv_bfloat16 d_Bh[(size_t)KIN*KIN], d_Bl[(size_t)KIN*KIN];   // Win^T [n][k]
__device__ __nv_bfloat16 d_h0h[MROWS*H_], d_h0l[MROWS*H_];               // h0 bf16 split
__device__ __nv_bfloat16 d_xh[(size_t)MROWS*KST], d_xl[(size_t)MROWS*KST];
__device__ __nv_bfloat16 d_wch[NCOLS*KST], d_wcl[NCOLS*KST];             // [Wt;Ws]^T [n][k]
__device__ __nv_bfloat16 d_uh[NCOLS*H_], d_ul[NCOLS*H_];                 // U^T [n][k]

__constant__ int c_zs[NG] = {0,1,1,3,4,5,6,7,8};

// ---------- base-ISA async/mma helpers (NO tcgen05 — toolchain targets compute_103 base) ----------
__device__ __forceinline__ uint32_t smem_u32(const void* p) {
    uint32_t a;
    asm("{ .reg .u64 t; cvta.to.shared.u64 t, %1; cvt.u32.u64 %0, t; }" : "=r"(a) : "l"(p));
    return a;
}
__device__ __forceinline__ void cpa16(uint32_t dst, const void* src) {
    asm volatile("cp.async.cg.shared.global [%0], [%1], 16;" :: "r"(dst), "l"(src));
}
#define CP_COMMIT() asm volatile("cp.async.commit_group;" ::: "memory")
#define CP_WAIT(n)  asm volatile("cp.async.wait_group %0;" :: "n"(n) : "memory")

#define LDSM4(r, a) \
    asm volatile("ldmatrix.sync.aligned.m8n8.x4.shared.b16 {%0,%1,%2,%3}, [%4];" \
        : "=r"((r)[0]), "=r"((r)[1]), "=r"((r)[2]), "=r"((r)[3]) : "r"(a))

#define MMA_BF16(d, a, b) \
    asm volatile("mma.sync.aligned.m16n8k16.row.col.f32.bf16.bf16.f32 " \
        "{%0,%1,%2,%3},{%4,%5,%6,%7},{%8,%9},{%0,%1,%2,%3};" \
        : "+f"((d)[0]), "+f"((d)[1]), "+f"((d)[2]), "+f"((d)[3]) \
        : "r"((a)[0]), "r"((a)[1]), "r"((a)[2]), "r"((a)[3]), "r"((b)[0]), "r"((b)[1]))

__device__ __forceinline__ void bsplit(float v, __nv_bfloat16& h, __nv_bfloat16& l) {
    h = __float2bfloat16(v);
    l = __float2bfloat16(v - __bfloat162float(h));
}
__device__ __forceinline__ void pack4(float4 v, uint2& uh, uint2& ul) {
    __nv_bfloat16 h0,h1,h2,h3,l0,l1,l2,l3;
    bsplit(v.x,h0,l0); bsplit(v.y,h1,l1); bsplit(v.z,h2,l2); bsplit(v.w,h3,l3);
    uh.x = (uint32_t)__bfloat16_as_ushort(h0) | ((uint32_t)__bfloat16_as_ushort(h1) << 16);
    uh.y = (uint32_t)__bfloat16_as_ushort(h2) | ((uint32_t)__bfloat16_as_ushort(h3) << 16);
    ul.x = (uint32_t)__bfloat16_as_ushort(l0) | ((uint32_t)__bfloat16_as_ushort(l1) << 16);
    ul.y = (uint32_t)__bfloat16_as_ushort(l2) | ((uint32_t)__bfloat16_as_ushort(l3) << 16);
}

// fast activation helpers (h2tanh name collides with cuda_fp16.hpp builtin)
__device__ __forceinline__ __half2 h2tanh_(__half2 x) {
    uint32_t xi = *(uint32_t*)&x, yo;
    asm("tanh.approx.f16x2 %0, %1;" : "=r"(yo) : "r"(xi));
    return *(__half2*)&yo;
}
// sigma(x) = 0.5*tanh(0.5x)+0.5, two lanes at once (approx)
__device__ __forceinline__ float2 gate_sig(__half2 x) {
    const __half2 h5 = __float2half2_rn(0.5f);
    __half2 g = __hfma2(h2tanh_(__hmul2(x, h5)), h5, h5);
    return __half22float2(g);
}

// ---------- prep kernels ----------
__global__ void k_cvt_enc(const float* __restrict__ A) {
    int i = blockIdx.x * 256 + threadIdx.x;          // 2048*1024 quads
    if (i >= 2048 * 1024) return;
    int r = i >> 10, c4 = (i & 1023) << 2;
    float4 v = make_float4(0.f,0.f,0.f,0.f);
    if (r < BT) v = *(const float4*)&A[(size_t)r * KIN + c4];
    uint2 uh, ul; pack4(v, uh, ul);
    size_t o = (size_t)r * KIN + c4;
    *(uint2*)&d_Ah[o] = uh; *(uint2*)&d_Al[o] = ul;
}
__global__ void k_trans_win(const float* __restrict__ W) {
    __shared__ float t[32][33];
    int n0 = blockIdx.x * 32, k0 = blockIdx.y * 32;
    int tx = threadIdx.x, ty = threadIdx.y;  // (32,8)
    #pragma unroll
    for (int j = 0; j < 32; j += 8)
        t[ty + j][tx] = W[(size_t)(k0 + ty + j) * KIN + n0 + tx];
    __syncthreads();
    #pragma unroll
    for (int j = 0; j < 32; j += 8) {
        float v = t[tx][ty + j];
        size_t o = (size_t)(n0 + ty + j) * KIN + k0 + tx;
        __nv_bfloat16 h, l; bsplit(v, h, l);
        d_Bh[o] = h; d_Bl[o] = l;
    }
}
// build Wcat^T [576 x 256] (Wt,Ws) and U^T [576 x 64]
__global__ void k_wcat2(const float* __restrict__ Wt, const float* __restrict__ Ws,
                        const float* __restrict__ U) {
    int i = blockIdx.x * 256 + threadIdx.x;   // 576*256 + 576*64 = 184320
    if (i >= NCOLS * (KST + H_)) return;
    if (i < NCOLS * KST) {
        int n = i / KST, k = i % KST;
        int g = n >> 6, h = n & 63;
        float v = (k < 192) ? Wt[(g * 192 + k) * 64 + h]
                            : Ws[(g * 64 + (k - 192)) * 64 + h];
        __nv_bfloat16 hh, ll; bsplit(v, hh, ll);
        d_wch[i] = hh; d_wcl[i] = ll;
    } else {
        int j = i - NCOLS * KST;
        int n = j / H_, k = j % H_;
        int g = n >> 6, h = n & 63;
        float v = U[(size_t)g * 4096 + k * 64 + h];
        __nv_bfloat16 hh, ll; bsplit(v, hh, ll);
        d_uh[j] = hh; d_ul[j] = ll;
    }
}
__global__ void k_gb2(const float* __restrict__ bb) {
    int i = blockIdx.x * 256 + threadIdx.x;
    if (i >= NG * 2048 * 64) return;
    int h = i & 63, m = (i >> 6) & 2047, g = i >> 17;
    d_gb2[i] = d_gtt[i] + bb[(size_t)g * 4096 + (m & 63) * 64 + h];
}

// zero the never-written pad slots of X (boundary t=0 / t=T-1 / n=0)
#define XPAD_TOTAL (131072 + 131072 + 129024)
__global__ void k_xinit() {
    int i = blockIdx.x * 256 + threadIdx.x;
    if (i >= XPAD_TOTAL) return;
    int row, col;
    if (i < 131072) {                 // sec0 pads: t == 0
        int b = i >> 12, n = (i >> 6) & 63, hh = i & 63;
        row = (b * T_) * 64 + n; col = hh;
    } else if (i < 262144) {          // sec2 pads: t == T-1
        int j = i - 131072;
        int b = j >> 12, n = (j >> 6) & 63, hh = j & 63;
        row = (b * T_ + T_ - 1) * 64 + n; col = 128 + hh;
    } else {                          // sec3 pads: n == 0
        int j = i - 262144;
        int bt = j >> 6, hh = j & 63;
        row = bt * 64; col = 192 + hh;
    }
    size_t o = (size_t)row * KST + col;
    d_xh[o] = __float2bfloat16(0.f);
    d_xl[o] = __float2bfloat16(0.f);
}

// initial scatter: X from h0 (secs 0..3)
__global__ void k_scatter0() {
    int i = blockIdx.x * 256 + threadIdx.x;   // MROWS*64
    if (i >= MROWS * 64) return;
    int hh = i & 63, r = i >> 6;
    int n = r & 63, bt = r >> 6, t = bt % T_;
    float v = d_h0[i];
    __nv_bfloat16 hb, lb; bsplit(v, hb, lb);
    size_t ro = (size_t)r * KST;
    d_xh[ro + 64 + hh] = hb;  d_xl[ro + 64 + hh] = lb;    // sec1 (self)
    if (t < T_ - 1) { size_t o = ro + (size_t)64*KST + hh;       d_xh[o] = hb; d_xl[o] = lb; }  // sec0 of t+1
    if (t > 0)      { size_t o = ro - (size_t)64*KST + 128 + hh; d_xh[o] = hb; d_xl[o] = lb; }  // sec2 of t-1
    if (n < NB - 1) { size_t o = ro + KST + 192 + hh;            d_xh[o] = hb; d_xl[o] = lb; }  // sec3 of n+1
}

// ---------- means / small gemms ----------
__global__ void k_mean_t() {
    int i = blockIdx.x * 256 + threadIdx.x;
    int hh = i & 63, n = (i >> 6) & 63, b = i >> 12;
    const float* p = d_h0 + ((size_t)(b * T_) * NB + n) * H_ + hh;
    float s = 0.f;
    for (int t = 0; t < T_; t++) s += p[(size_t)t * NB * H_];
    d_gt[i] = s * (1.0f / T_);
}
__global__ void k_mean_n() {
    int i = blockIdx.x * 256 + threadIdx.x;
    int hh = i & 63, bt = i >> 6;
    const float* p = d_h0 + (size_t)bt * NB * H_ + hh;
    float s = 0.f;
    for (int n = 0; n < NB; n++) s += p[n * H_];
    d_gs[i] = s * (1.0f / NB);
}
__global__ __launch_bounds__(256) void k_ninegemm(int which, const float* __restrict__ Wbase) {
    const int g = blockIdx.x;
    const int m0 = blockIdx.y * 64;
    const float* X = which ? d_gs : d_gt;
    float* out = which ? d_gst : d_gtt;
    const int M = which ? BT : (B_ * NB);
    const float* Wg = Wbase + (size_t)(which ? c_zs[g] : g) * 4096;
    __shared__ float XT[64][68];
    __shared__ float Wsm[64][68];
    const int tid = threadIdx.x;
    for (int i = tid; i < 4096; i += 256) {
        int r = i >> 6, k = i & 63;
        XT[k][r] = (m0 + r < M) ? X[(size_t)(m0 + r) * 64 + k] : 0.f;
        Wsm[r][k] = Wg[i];
    }
    __syncthreads();
    const int tx = tid & 15, ty = tid >> 4;
    float acc[4][4];
    #pragma unroll
    for (int i = 0; i < 4; i++)
        #pragma unroll
        for (int j = 0; j < 4; j++) acc[i][j] = 0.f;
    #pragma unroll 16
    for (int kk = 0; kk < 64; kk++) {
        float4 a = *(const float4*)&XT[kk][ty * 4];
        float4 w = *(const float4*)&Wsm[kk][tx * 4];
        float av[4] = {a.x,a.y,a.z,a.w}, wv[4] = {w.x,w.y,w.z,w.w};
        #pragma unroll
        for (int i = 0; i < 4; i++)
            #pragma unroll
            for (int j = 0; j < 4; j++) acc[i][j] = fmaf(av[i], wv[j], acc[i][j]);
    }
    #pragma unroll
    for (int i = 0; i < 4; i++) {
        int row = m0 + ty * 4 + i;
        if (row >= M) break;
        float4 v = make_float4(acc[i][0], acc[i][1], acc[i][2], acc[i][3]);
        *(float4*)&out[((size_t)g * M + row) * 64 + tx * 4] = v;
    }
}

// ============ mma.sync input GEMM: h0 = enc @ Win + bias (2-stage, 2 CTAs/SM) ============
__device__ __forceinline__ void gin_load(uint32_t sb, int st, int k0, int row0, int col0, int tid) {
    uint32_t base = sb + (uint32_t)st * 40960u;
    #pragma unroll
    for (int w = 0; w < 8; w++) {
        int idx = tid + w * 256;        // 0..2047
        int t = idx >> 9;               // 0:Ah 1:Al 2:Bh 3:Bl
        int j = idx & 511;
        int r = j >> 2, c = j & 3;
        const __nv_bfloat16* g;
        int rb;
        if (t == 0)      { g = d_Ah; rb = row0; }
        else if (t == 1) { g = d_Al; rb = row0; }
        else if (t == 2) { g = d_Bh; rb = col0; }
        else             { g = d_Bl; rb = col0; }
        cpa16(base + (uint32_t)t * 10240u + (uint32_t)r * 80u + (uint32_t)c * 16u,
              g + (size_t)(rb + r) * KIN + k0 + c * 8);
    }
    CP_COMMIT();
}
__global__ __launch_bounds__(256) void k_gemm_in_m(const float* __restrict__ bias) {
    extern __shared__ __align__(128) char smraw[];
    uint32_t sb = smem_u32(smraw);
    const int tid = threadIdx.x, wid = tid >> 5, lane = tid & 31;
    const int row0 = blockIdx.y << 7, col0 = blockIdx.x << 7;
    const int wm = (wid >> 2) * 64, wn = (wid & 3) * 32;

    float acc[4][4][4];
    #pragma unroll
    for (int a = 0; a < 4; a++)
        #pragma unroll
        for (int b = 0; b < 4; b++)
            #pragma unroll
            for (int cdx = 0; cdx < 4; cdx++) acc[a][b][cdx] = 0.f;

    gin_load(sb, 0, 0, row0, col0, tid);
    for (int ck = 0; ck < 128; ck++) {
        int s = ck & 1;
        if (ck + 1 < 128) { gin_load(sb, s ^ 1, (ck + 1) * 32, row0, col0, tid); CP_WAIT(1); }
        else CP_WAIT(0);
        __syncthreads();
        uint32_t ab = sb + (uint32_t)s * 40960u, bb = ab + 20480u;
        #pragma unroll
        for (int half = 0; half < 2; half++) {
            uint32_t ah[4][4], al[4][4], bh[4][2], bl[4][2];
            #pragma unroll
            for (int mt = 0; mt < 4; mt++) {
                uint32_t ad = ab + (uint32_t)(wm + mt * 16 + (lane & 15)) * 80u
                                 + (uint32_t)(half * 2 + (lane >> 4)) * 16u;
                LDSM4(ah[mt], ad);
                LDSM4(al[mt], ad + 10240u);
            }
            #pragma unroll
            for (int ng = 0; ng < 2; ng++) {
                uint32_t bd = bb + (uint32_t)(wn + ng * 16 + (lane & 7) + ((lane & 16) ? 8 : 0)) * 80u
                                 + (uint32_t)(half * 2 + ((lane >> 3) & 1)) * 16u;
                uint32_t t4[4];
                LDSM4(t4, bd);
                bh[ng*2][0] = t4[0]; bh[ng*2][1] = t4[1]; bh[ng*2+1][0] = t4[2]; bh[ng*2+1][1] = t4[3];
                LDSM4(t4, bd + 10240u);
                bl[ng*2][0] = t4[0]; bl[ng*2][1] = t4[1]; bl[ng*2+1][0] = t4[2]; bl[ng*2+1][1] = t4[3];
            }
            #pragma unroll
            for (int mt = 0; mt < 4; mt++)
                #pragma unroll
                for (int nt = 0; nt < 4; nt++) {
                    MMA_BF16(acc[mt][nt], ah[mt], bh[nt]);
                    MMA_BF16(acc[mt][nt], ah[mt], bl[nt]);
                    MMA_BF16(acc[mt][nt], al[mt], bh[nt]);
                }
        }
        __syncthreads();
    }
    const int r0 = lane >> 2, cf = (lane & 3) * 2;
    #pragma unroll
    for (int mt = 0; mt < 4; mt++)
        #pragma unroll
        for (int i = 0; i < 2; i++) {
            int m = row0 + wm + mt * 16 + r0 + i * 8;
            if (m < BT) {
                #pragma unroll
                for (int nt = 0; nt < 4; nt++) {
                    int cg = col0 + wn + nt * 8 + cf;
                    float2 v;
                    v.x = acc[mt][nt][i*2+0] + bias[cg];
                    v.y = acc[mt][nt][i*2+1] + bias[cg+1];
                    size_t o = (size_t)m * KIN + cg;
                    *(float2*)&d_h0[o] = v;
                    // bf16 split of h0 for the const-pass GEMM (same linear layout as [MROWS][64])
                    __nv_bfloat16 hx, lx, hy, ly;
                    bsplit(v.x, hx, lx); bsplit(v.y, hy, ly);
                    uint32_t uh = (uint32_t)__bfloat16_as_ushort(hx) | ((uint32_t)__bfloat16_as_ushort(hy) << 16);
                    uint32_t ul = (uint32_t)__bfloat16_as_ushort(lx) | ((uint32_t)__bfloat16_as_ushort(ly) << 16);
                    *(uint32_t*)&d_h0h[o] = uh;
                    *(uint32_t*)&d_h0l[o] = ul;
                }
            }
        }
}

// ============ const-pass GEMM: PCONST = h0 @ U^T + gb2 + gst (fp16 out) ============
__device__ __forceinline__ void cg_load(uint32_t sb, int st, int k0, int row0, int gg, int tid) {
    uint32_t base = sb + (uint32_t)st * 51200u;
    #pragma unroll
    for (int w = 0; w < 10; w++) {
        int idx = tid + w * 256;        // 0..2559
        if (idx < 1024) {
            int t = idx >> 9, j = idx & 511, r = j >> 2, c = j & 3;
            const __nv_bfloat16* g = t ? d_h0l : d_h0h;
            cpa16(base + (uint32_t)t * 10240u + (uint32_t)r * 80u + (uint32_t)c * 16u,
                  g + (size_t)(row0 + r) * 64 + k0 + c * 8);
        } else {
            int j2 = idx - 1024;        // 0..1535
            int t = j2 >= 768 ? 1 : 0;
            int j = j2 - t * 768, r = j >> 2, c = j & 3;
            const __nv_bfloat16* g = t ? d_ul : d_uh;
            cpa16(base + 20480u + (uint32_t)t * 15360u + (uint32_t)r * 80u + (uint32_t)c * 16u,
                  g + (size_t)(gg * 192 + r) * 64 + k0 + c * 8);
        }
    }
    CP_COMMIT();
}
__global__ __launch_bounds__(256) void k_cgemm() {
    extern __shared__ __align__(128) char smraw[];
    uint32_t sb = smem_u32(smraw);
    const int tid = threadIdx.x, wid = tid >> 5, lane = tid & 31;
    const int gg = blockIdx.x;                 // 0..2
    const int row0 = blockIdx.y << 7;
    const int wm = (wid >> 2) * 64, wn = (wid & 3) * 48;

    float acc[4][6][4];
    #pragma unroll
    for (int a = 0; a < 4; a++)
        #pragma unroll
        for (int b = 0; b < 6; b++)
            #pragma unroll
            for (int cdx = 0; cdx < 4; cdx++) acc[a][b][cdx] = 0.f;

    cg_load(sb, 0, 0, row0, gg, tid);
    for (int ck = 0; ck < 2; ck++) {
        int s = ck & 1;
        if (ck + 1 < 2) { cg_load(sb, s ^ 1, 32, row0, gg, tid); CP_WAIT(1); }
        else CP_WAIT(0);
        __syncthreads();
        uint32_t ab = sb + (uint32_t)s * 51200u, bb = ab + 20480u;
        #pragma unroll
        for (int half = 0; half < 2; half++) {
            uint32_t ah[4][4], al[4][4], bh[6][2], bl[6][2];
            #pragma unroll
            for (int mt = 0; mt < 4; mt++) {
                uint32_t ad = ab + (uint32_t)(wm + mt * 16 + (lane & 15)) * 80u
                                 + (uint32_t)(half * 2 + (lane >> 4)) * 16u;
                LDSM4(ah[mt], ad);
                LDSM4(al[mt], ad + 10240u);
            }
            #pragma unroll
            for (int ng = 0; ng < 3; ng++) {
                uint32_t bd = bb + (uint32_t)(wn + ng * 16 + (lane & 7) + ((lane & 16) ? 8 : 0)) * 80u
                                 + (uint32_t)(half * 2 + ((lane >> 3) & 1)) * 16u;
                uint32_t t4[4];
                LDSM4(t4, bd);
                bh[ng*2][0] = t4[0]; bh[ng*2][1] = t4[1]; bh[ng*2+1][0] = t4[2]; bh[ng*2+1][1] = t4[3];
                LDSM4(t4, bd + 15360u);
                bl[ng*2][0] = t4[0]; bl[ng*2][1] = t4[1]; bl[ng*2+1][0] = t4[2]; bl[ng*2+1][1] = t4[3];
            }
            #pragma unroll
            for (int mt = 0; mt < 4; mt++)
                #pragma unroll
                for (int nt = 0; nt < 6; nt++) {
                    MMA_BF16(acc[mt][nt], ah[mt], bh[nt]);
                    MMA_BF16(acc[mt][nt], ah[mt], bl[nt]);
                    MMA_BF16(acc[mt][nt], al[mt], bh[nt]);
                }
        }
        __syncthreads();
    }
    const int r0 = lane >> 2, cf = (lane & 3) * 2;
    #pragma unroll
    for (int mt = 0; mt < 4; mt++)
        #pragma unroll
        for (int i = 0; i < 2; i++) {
            int m = row0 + wm + mt * 16 + r0 + i * 8;
            int bone = m & 63, bt = m >> 6, b = bt / T_;
            #pragma unroll
            for (int nt = 0; nt < 6; nt++) {
                int nc = gg * 192 + wn + nt * 8 + cf;
                int g = nc >> 6, h = nc & 63;
                float2 a1 = *(const float2*)&d_gb2[(((size_t)g * 2048) + b * 64 + bone) * 64 + h];
                float2 a2 = *(const float2*)&d_gst[(((size_t)g * BT) + bt) * 64 + h];
                __half2 v = __floats2half2_rn(acc[mt][nt][i*2+0] + a1.x + a2.x,
                                              acc[mt][nt][i*2+1] + a1.y + a2.y);
                *(__half2*)&d_pcst[(size_t)m * NCOLS + nc] = v;
            }
        }
}

// ============ mma.sync step GEMM: PRE = X(256) @ Wcat^T + PCONST (fp16 out, 2-stage) ============
__device__ __forceinline__ void step_load(uint32_t sb, int st, int k0, int row0, int gg, int tid) {
    uint32_t base = sb + (uint32_t)st * 51200u;
    #pragma unroll
    for (int w = 0; w < 10; w++) {
        int idx = tid + w * 256;        // 0..2559
        if (idx < 1024) {
            int t = idx >> 9, j = idx & 511, r = j >> 2, c = j & 3;
            const __nv_bfloat16* g = t ? d_xl : d_xh;
            cpa16(base + (uint32_t)t * 10240u + (uint32_t)r * 80u + (uint32_t)c * 16u,
                  g + (size_t)(row0 + r) * KST + k0 + c * 8);
        } else {
            int j2 = idx - 1024;        // 0..1535
            int t = j2 >= 768 ? 1 : 0;
            int j = j2 - t * 768, r = j >> 2, c = j & 3;
            const __nv_bfloat16* g = t ? d_wcl : d_wch;
            cpa16(base + 20480u + (uint32_t)t * 15360u + (uint32_t)r * 80u + (uint32_t)c * 16u,
                  g + (size_t)(gg * 192 + r) * KST + k0 + c * 8);
        }
    }
    CP_COMMIT();
}
__global__ __launch_bounds__(256) void k_stepgemm_m() {
    extern __shared__ __align__(128) char smraw[];
    uint32_t sb = smem_u32(smraw);
    const int tid = threadIdx.x, wid = tid >> 5, lane = tid & 31;
    const int gg = blockIdx.x;                 // 0..2
    const int row0 = blockIdx.y << 7;          // 1008 tiles
    const int wm = (wid >> 2) * 64, wn = (wid & 3) * 48;

    float acc[4][6][4];
    #pragma unroll
    for (int a = 0; a < 4; a++)
        #pragma unroll
        for (int b = 0; b < 6; b++)
            #pragma unroll
            for (int cdx = 0; cdx < 4; cdx++) acc[a][b][cdx] = 0.f;

    step_load(sb, 0, 0, row0, gg, tid);
    for (int ck = 0; ck < 8; ck++) {
        int s = ck & 1;
        if (ck + 1 < 8) { step_load(sb, s ^ 1, (ck + 1) * 32, row0, gg, tid); CP_WAIT(1); }
        else CP_WAIT(0);
        __syncthreads();
        uint32_t ab = sb + (uint32_t)s * 51200u, bb = ab + 20480u;
        #pragma unroll
        for (int half = 0; half < 2; half++) {
            uint32_t ah[4][4], al[4][4], bh[6][2], bl[6][2];
            #pragma unroll
            for (int mt = 0; mt < 4; mt++) {
                uint32_t ad = ab + (uint32_t)(wm + mt * 16 + (lane & 15)) * 80u
                                 + (uint32_t)(half * 2 + (lane >> 4)) * 16u;
                LDSM4(ah[mt], ad);
                LDSM4(al[mt], ad + 10240u);
            }
            #pragma unroll
            for (int ng = 0; ng < 3; ng++) {
                uint32_t bd = bb + (uint32_t)(wn + ng * 16 + (lane & 7) + ((lane & 16) ? 8 : 0)) * 80u
                                 + (uint32_t)(half * 2 + ((lane >> 3) & 1)) * 16u;
                uint32_t t4[4];
                LDSM4(t4, bd);
                bh[ng*2][0] = t4[0]; bh[ng*2][1] = t4[1]; bh[ng*2+1][0] = t4[2]; bh[ng*2+1][1] = t4[3];
                LDSM4(t4, bd + 15360u);
                bl[ng*2][0] = t4[0]; bl[ng*2][1] = t4[1]; bl[ng*2+1][0] = t4[2]; bl[ng*2+1][1] = t4[3];
            }
            #pragma unroll
            for (int mt = 0; mt < 4; mt++)
                #pragma unroll
                for (int nt = 0; nt < 6; nt++) {
                    MMA_BF16(acc[mt][nt], ah[mt], bh[nt]);
                    MMA_BF16(acc[mt][nt], ah[mt], bl[nt]);
                    MMA_BF16(acc[mt][nt], al[mt], bh[nt]);
                }
        }
        __syncthreads();
    }
    const int r0 = lane >> 2, cf = (lane & 3) * 2;
    #pragma unroll
    for (int mt = 0; mt < 4; mt++)
        #pragma unroll
        for (int i = 0; i < 2; i++) {
            int m = row0 + wm + mt * 16 + r0 + i * 8;
            #pragma unroll
            for (int nt = 0; nt < 6; nt++) {
                int nc = gg * 192 + wn + nt * 8 + cf;
                float2 pc = __half22float2(*(const __half2*)&d_pcst[(size_t)m * NCOLS + nc]);
                __half2 v = __floats2half2_rn(acc[mt][nt][i*2+0] + pc.x,
                                              acc[mt][nt][i*2+1] + pc.y);
                *(__half2*)&d_pre[(size_t)m * NCOLS + nc] = v;
            }
        }
}

// ---------- fused cell update (2 elems/thread) + scatter into X ----------
// gates: f16 tanh.approx; c_n and output tanh: accurate fp32 (accuracy headroom)
__global__ void k_cell3(const float* __restrict__ c_old, float* __restrict__ c_new,
                        float* __restrict__ hout, int do_scatter) {
    int i2 = blockIdx.x * 256 + threadIdx.x;   // MROWS*32 pairs
    int hh = (i2 & 31) << 1;                   // 0,2,..,62
    int r = i2 >> 5;
    int n = r & 63, bt = r >> 6;
    int t = bt % T_, b = bt / T_;
    const __half* pb = d_pre + (size_t)r * NCOLS + hh;
    float2 i_n  = gate_sig(*(const __half2*)(pb + 0));
    float2 f_lt = gate_sig(*(const __half2*)(pb + 64));
    float2 f_ft = gate_sig(*(const __half2*)(pb + 128));
    float2 f_rt = gate_sig(*(const __half2*)(pb + 192));
    float2 f_s  = gate_sig(*(const __half2*)(pb + 256));
    float2 f_gt = gate_sig(*(const __half2*)(pb + 320));
    float2 f_gs = gate_sig(*(const __half2*)(pb + 384));
    float2 o_n  = gate_sig(*(const __half2*)(pb + 448));
    float2 cn_pre = __half22float2(*(const __half2*)(pb + 512));
    float2 c_nv;
    c_nv.x = tanhf(cn_pre.x);
    c_nv.y = tanhf(cn_pre.y);
    int i = r * 64 + hh;
    float2 cc  = *(const float2*)&c_old[i];
    float2 ctb = make_float2(0.f, 0.f), cta = ctb, csb = ctb;
    if (t > 0)      ctb = *(const float2*)&c_old[i - 4096];
    if (t < T_ - 1) cta = *(const float2*)&c_old[i + 4096];
    if (n > 0)      csb = *(const float2*)&c_old[i - 64];
    float2 cgt = *(const float2*)&d_gt[(b * NB + n) * H_ + hh];
    float2 cgs = *(const float2*)&d_gs[bt * H_ + hh];
    float2 c;
    c.x = f_lt.x*ctb.x + f_ft.x*cc.x + f_rt.x*cta.x + f_s.x*csb.x
        + f_gt.x*cgt.x + f_gs.x*cgs.x + c_nv.x*i_n.x;
    c.y = f_lt.y*ctb.y + f_ft.y*cc.y + f_rt.y*cta.y + f_s.y*csb.y
        + f_gt.y*cgt.y + f_gs.y*cgs.y + c_nv.y*i_n.y;
    if (c_new) *(float2*)&c_new[i] = c;
    float2 hv;
    hv.x = o_n.x * tanhf(c.x);
    hv.y = o_n.y * tanhf(c.y);
    if (hout) *(float2*)&hout[i] = hv;
    if (do_scatter) {
        __nv_bfloat16 h0v, l0v, h1v, l1v;
        bsplit(hv.x, h0v, l0v); bsplit(hv.y, h1v, l1v);
        uint32_t uh = (uint32_t)__bfloat16_as_ushort(h0v) | ((uint32_t)__bfloat16_as_ushort(h1v) << 16);
        uint32_t ul = (uint32_t)__bfloat16_as_ushort(l0v) | ((uint32_t)__bfloat16_as_ushort(l1v) << 16);
        size_t ro = (size_t)r * KST;
        *(uint32_t*)&d_xh[ro + 64 + hh] = uh;
        *(uint32_t*)&d_xl[ro + 64 + hh] = ul;                                              // sec1
        if (t < T_ - 1) { size_t o = ro + (size_t)64*KST + hh;
                          *(uint32_t*)&d_xh[o] = uh; *(uint32_t*)&d_xl[o] = ul; }          // sec0 of t+1
        if (t > 0)      { size_t o = ro - (size_t)64*KST + 128 + hh;
                          *(uint32_t*)&d_xh[o] = uh; *(uint32_t*)&d_xl[o] = ul; }          // sec2 of t-1
        if (n < NB - 1) { size_t o = ro + KST + 192 + hh;
                          *(uint32_t*)&d_xh[o] = uh; *(uint32_t*)&d_xl[o] = ul; }          // sec3 of n+1
    }
}

extern "C" void kernel_launch(void* const* d_in, const int* in_sizes, int n_in,
                              void* d_out, int out_size) {
    const float* enc = (const float*)d_in[0];
    const float* Win = (const float*)d_in[2];
    const float* bin = (const float*)d_in[3];
    const float* U   = (const float*)d_in[4];
    const float* Wt  = (const float*)d_in[5];
    const float* Ws  = (const float*)d_in[6];
    const float* Zt  = (const float*)d_in[7];
    const float* Zs  = (const float*)d_in[8];
    const float* bb  = (const float*)d_in[9];
    float* out = (float*)d_out;

    cudaFuncSetAttribute(k_gemm_in_m,  cudaFuncAttributeMaxDynamicSharedMemorySize, 81920);
    cudaFuncSetAttribute(k_stepgemm_m, cudaFuncAttributeMaxDynamicSharedMemorySize, 102400);
    cudaFuncSetAttribute(k_cgemm,      cudaFuncAttributeMaxDynamicSharedMemorySize, 102400);

    void* c_sym = nullptr;
    cudaGetSymbolAddress(&c_sym, d_c);
    float* c0 = (float*)c_sym;
    float* c1 = c0 + (size_t)MROWS * H_;
    void* h0_sym = nullptr;
    cudaGetSymbolAddress(&h0_sym, d_h0);
    float* h0p = (float*)h0_sym;

    k_xinit<<<(XPAD_TOTAL + 255) / 256, 256>>>();
    k_cvt_enc<<<(2048 * 1024) / 256, 256>>>(enc);
    k_trans_win<<<dim3(128, 128), dim3(32, 8)>>>(Win);
    k_wcat2<<<(NCOLS * (KST + H_) + 255) / 256, 256>>>(Wt, Ws, U);
    k_gemm_in_m<<<dim3(32, 16), 256, 81920>>>(bin);
    k_mean_t<<<(B_ * NB * H_) / 256, 256>>>();
    k_mean_n<<<(BT * H_) / 256, 256>>>();
    k_ninegemm<<<dim3(NG, 32), 256>>>(0, Zt);
    k_ninegemm<<<dim3(NG, 32), 256>>>(1, Zs);
    k_gb2<<<(NG * 2048 * 64) / 256, 256>>>(bb);
    k_scatter0<<<(MROWS * 64) / 256, 256>>>();
    k_cgemm<<<dim3(3, MROWS / 128), 256, 102400>>>();   // PCONST once

    // step 0: c_old = h0, c_new = c0
    k_stepgemm_m<<<dim3(3, MROWS / 128), 256, 102400>>>();
    k_cell3<<<(MROWS * 32) / 256, 256>>>(h0p, c0, nullptr, 1);
    // step 1: c_old = c0, c_new = c1
    k_stepgemm_m<<<dim3(3, MROWS / 128), 256, 102400>>>();
    k_cell3<<<(MROWS * 32) / 256, 256>>>(c0, c1, nullptr, 1);
    // step 2: c_old = c1, no c_new, h -> out, no scatter
    k_stepgemm_m<<<dim3(3, MROWS / 128), 256, 102400>>>();
    k_cell3<<<(MROWS * 32) / 256, 256>>>(c1, nullptr, out, 0);
}

// round 16
// speedup vs baseline: 1.0370x; 1.0370x over previous
#include <cuda_runtime.h>
#include <cuda_bf16.h>
#include <cuda_fp16.h>
#include <math.h>
#include <stdint.h>

#define B_ 32
#define T_ 63
#define NB 64
#define H_ 64
#define KIN 4096
#define BT (B_*T_)            // 2016
#define MROWS (BT*NB)         // 129024
#define NG 9
#define NCOLS (NG*H_)         // 576
#define KST 320               // [h(t-1); h; h(t+1); h(n-1); h0] x 64 (weights K)

__device__ float d_h0[MROWS*H_];                     // input projection output (fp32)
__device__ float d_c[2][MROWS*H_];                   // cell state ping-pong
__device__ __half d_pre[(size_t)MROWS*NCOLS];        // gate pre-activations (fp16)
__device__ float d_gt[B_*NB*H_];
__device__ float d_gs[BT*H_];
__device__ float d_gtt[NG*B_*NB*H_];
__device__ float d_gst[NG*BT*H_];
__device__ float d_gb2[NG*B_*NB*H_];                 // gtt + bias
__device__ __nv_bfloat16 d_Ah[2048*KIN], d_Al[2048*KIN];
__device__ __nv_bfloat16 d_Bh[(size_t)KIN*KIN], d_Bl[(size_t)KIN*KIN];   // Win^T [n][k]
__device__ __nv_bfloat16 d_h0h[MROWS*H_], d_h0l[MROWS*H_];               // h0 bf16 split (fixed)
__device__ __nv_bfloat16 d_hh[MROWS*H_],  d_hl[MROWS*H_];                // current h bf16 split
__device__ __nv_bfloat16 d_wch[NCOLS*KST], d_wcl[NCOLS*KST];             // [Wt;Ws;U]^T [n][k]

__constant__ int c_zs[NG] = {0,1,1,3,4,5,6,7,8};

// ---------- base-ISA async/mma helpers (NO tcgen05 — toolchain targets compute_103 base) ----------
__device__ __forceinline__ uint32_t smem_u32(const void* p) {
    uint32_t a;
    asm("{ .reg .u64 t; cvta.to.shared.u64 t, %1; cvt.u32.u64 %0, t; }" : "=r"(a) : "l"(p));
    return a;
}
__device__ __forceinline__ void cpa16(uint32_t dst, const void* src) {
    asm volatile("cp.async.cg.shared.global [%0], [%1], 16;" :: "r"(dst), "l"(src));
}
// predicated: pred=false -> zero-fill 16B (src-size 0)
__device__ __forceinline__ void cpa16p(uint32_t dst, const void* src, bool p) {
    int sz = p ? 16 : 0;
    asm volatile("cp.async.cg.shared.global [%0], [%1], 16, %2;" :: "r"(dst), "l"(src), "r"(sz));
}
#define CP_COMMIT() asm volatile("cp.async.commit_group;" ::: "memory")
#define CP_WAIT(n)  asm volatile("cp.async.wait_group %0;" :: "n"(n) : "memory")

#define LDSM4(r, a) \
    asm volatile("ldmatrix.sync.aligned.m8n8.x4.shared.b16 {%0,%1,%2,%3}, [%4];" \
        : "=r"((r)[0]), "=r"((r)[1]), "=r"((r)[2]), "=r"((r)[3]) : "r"(a))

#define MMA_BF16(d, a, b) \
    asm volatile("mma.sync.aligned.m16n8k16.row.col.f32.bf16.bf16.f32 " \
        "{%0,%1,%2,%3},{%4,%5,%6,%7},{%8,%9},{%0,%1,%2,%3};" \
        : "+f"((d)[0]), "+f"((d)[1]), "+f"((d)[2]), "+f"((d)[3]) \
        : "r"((a)[0]), "r"((a)[1]), "r"((a)[2]), "r"((a)[3]), "r"((b)[0]), "r"((b)[1]))

__device__ __forceinline__ void bsplit(float v, __nv_bfloat16& h, __nv_bfloat16& l) {
    h = __float2bfloat16(v);
    l = __float2bfloat16(v - __bfloat162float(h));
}
__device__ __forceinline__ void pack4(float4 v, uint2& uh, uint2& ul) {
    __nv_bfloat16 h0,h1,h2,h3,l0,l1,l2,l3;
    bsplit(v.x,h0,l0); bsplit(v.y,h1,l1); bsplit(v.z,h2,l2); bsplit(v.w,h3,l3);
    uh.x = (uint32_t)__bfloat16_as_ushort(h0) | ((uint32_t)__bfloat16_as_ushort(h1) << 16);
    uh.y = (uint32_t)__bfloat16_as_ushort(h2) | ((uint32_t)__bfloat16_as_ushort(h3) << 16);
    ul.x = (uint32_t)__bfloat16_as_ushort(l0) | ((uint32_t)__bfloat16_as_ushort(l1) << 16);
    ul.y = (uint32_t)__bfloat16_as_ushort(l2) | ((uint32_t)__bfloat16_as_ushort(l3) << 16);
}

// fast activation helpers (h2tanh name collides with cuda_fp16.hpp builtin)
__device__ __forceinline__ __half2 h2tanh_(__half2 x) {
    uint32_t xi = *(uint32_t*)&x, yo;
    asm("tanh.approx.f16x2 %0, %1;" : "=r"(yo) : "r"(xi));
    return *(__half2*)&yo;
}
__device__ __forceinline__ float ftanh_(float x) {
    float y;
    asm("tanh.approx.f32 %0, %1;" : "=f"(y) : "f"(x));
    return y;
}
// sigma(x) = 0.5*tanh(0.5x)+0.5, two lanes at once (approx)
__device__ __forceinline__ float2 gate_sig(__half2 x) {
    const __half2 h5 = __float2half2_rn(0.5f);
    __half2 g = __hfma2(h2tanh_(__hmul2(x, h5)), h5, h5);
    return __half22float2(g);
}

// ---------- prep kernels ----------
__global__ void k_cvt_enc(const float* __restrict__ A) {
    int i = blockIdx.x * 256 + threadIdx.x;          // 2048*1024 quads
    if (i >= 2048 * 1024) return;
    int r = i >> 10, c4 = (i & 1023) << 2;
    float4 v = make_float4(0.f,0.f,0.f,0.f);
    if (r < BT) v = *(const float4*)&A[(size_t)r * KIN + c4];
    uint2 uh, ul; pack4(v, uh, ul);
    size_t o = (size_t)r * KIN + c4;
    *(uint2*)&d_Ah[o] = uh; *(uint2*)&d_Al[o] = ul;
}
__global__ void k_trans_win(const float* __restrict__ W) {
    __shared__ float t[32][33];
    int n0 = blockIdx.x * 32, k0 = blockIdx.y * 32;
    int tx = threadIdx.x, ty = threadIdx.y;  // (32,8)
    #pragma unroll
    for (int j = 0; j < 32; j += 8)
        t[ty + j][tx] = W[(size_t)(k0 + ty + j) * KIN + n0 + tx];
    __syncthreads();
    #pragma unroll
    for (int j = 0; j < 32; j += 8) {
        float v = t[tx][ty + j];
        size_t o = (size_t)(n0 + ty + j) * KIN + k0 + tx;
        __nv_bfloat16 h, l; bsplit(v, h, l);
        d_Bh[o] = h; d_Bl[o] = l;
    }
}
// build [Wt;Ws;U]^T [576 x 320]
__global__ void k_wcat2(const float* __restrict__ Wt, const float* __restrict__ Ws,
                        const float* __restrict__ U) {
    int i = blockIdx.x * 256 + threadIdx.x;   // 576*320
    if (i >= NCOLS * KST) return;
    int n = i / KST, k = i % KST;
    int g = n >> 6, h = n & 63;
    float v = (k < 192) ? Wt[(g * 192 + k) * 64 + h]
            : (k < 256) ? Ws[(g * 64 + (k - 192)) * 64 + h]
                        : U [(g * 64 + (k - 256)) * 64 + h];
    __nv_bfloat16 hh, ll; bsplit(v, hh, ll);
    d_wch[i] = hh; d_wcl[i] = ll;
}
__global__ void k_gb2(const float* __restrict__ bb) {
    int i = blockIdx.x * 256 + threadIdx.x;
    if (i >= NG * 2048 * 64) return;
    int h = i & 63, m = (i >> 6) & 2047, g = i >> 17;
    d_gb2[i] = d_gtt[i] + bb[(size_t)g * 4096 + (m & 63) * 64 + h];
}

// ---------- means / small gemms ----------
__global__ void k_mean_t() {
    int i = blockIdx.x * 256 + threadIdx.x;
    int hh = i & 63, n = (i >> 6) & 63, b = i >> 12;
    const float* p = d_h0 + ((size_t)(b * T_) * NB + n) * H_ + hh;
    float s = 0.f;
    for (int t = 0; t < T_; t++) s += p[(size_t)t * NB * H_];
    d_gt[i] = s * (1.0f / T_);
}
__global__ void k_mean_n() {
    int i = blockIdx.x * 256 + threadIdx.x;
    int hh = i & 63, bt = i >> 6;
    const float* p = d_h0 + (size_t)bt * NB * H_ + hh;
    float s = 0.f;
    for (int n = 0; n < NB; n++) s += p[n * H_];
    d_gs[i] = s * (1.0f / NB);
}
__global__ __launch_bounds__(256) void k_ninegemm(int which, const float* __restrict__ Wbase) {
    const int g = blockIdx.x;
    const int m0 = blockIdx.y * 64;
    const float* X = which ? d_gs : d_gt;
    float* out = which ? d_gst : d_gtt;
    const int M = which ? BT : (B_ * NB);
    const float* Wg = Wbase + (size_t)(which ? c_zs[g] : g) * 4096;
    __shared__ float XT[64][68];
    __shared__ float Wsm[64][68];
    const int tid = threadIdx.x;
    for (int i = tid; i < 4096; i += 256) {
        int r = i >> 6, k = i & 63;
        XT[k][r] = (m0 + r < M) ? X[(size_t)(m0 + r) * 64 + k] : 0.f;
        Wsm[r][k] = Wg[i];
    }
    __syncthreads();
    const int tx = tid & 15, ty = tid >> 4;
    float acc[4][4];
    #pragma unroll
    for (int i = 0; i < 4; i++)
        #pragma unroll
        for (int j = 0; j < 4; j++) acc[i][j] = 0.f;
    #pragma unroll 16
    for (int kk = 0; kk < 64; kk++) {
        float4 a = *(const float4*)&XT[kk][ty * 4];
        float4 w = *(const float4*)&Wsm[kk][tx * 4];
        float av[4] = {a.x,a.y,a.z,a.w}, wv[4] = {w.x,w.y,w.z,w.w};
        #pragma unroll
        for (int i = 0; i < 4; i++)
            #pragma unroll
            for (int j = 0; j < 4; j++) acc[i][j] = fmaf(av[i], wv[j], acc[i][j]);
    }
    #pragma unroll
    for (int i = 0; i < 4; i++) {
        int row = m0 + ty * 4 + i;
        if (row >= M) break;
        float4 v = make_float4(acc[i][0], acc[i][1], acc[i][2], acc[i][3]);
        *(float4*)&out[((size_t)g * M + row) * 64 + tx * 4] = v;
    }
}

// ============ mma.sync input GEMM: h0 = enc @ Win + bias (2-stage, 2 CTAs/SM) ============
__device__ __forceinline__ void gin_load(uint32_t sb, int st, int k0, int row0, int col0, int tid) {
    uint32_t base = sb + (uint32_t)st * 40960u;
    #pragma unroll
    for (int w = 0; w < 8; w++) {
        int idx = tid + w * 256;        // 0..2047
        int t = idx >> 9;               // 0:Ah 1:Al 2:Bh 3:Bl
        int j = idx & 511;
        int r = j >> 2, c = j & 3;
        const __nv_bfloat16* g;
        int rb;
        if (t == 0)      { g = d_Ah; rb = row0; }
        else if (t == 1) { g = d_Al; rb = row0; }
        else if (t == 2) { g = d_Bh; rb = col0; }
        else             { g = d_Bl; rb = col0; }
        cpa16(base + (uint32_t)t * 10240u + (uint32_t)r * 80u + (uint32_t)c * 16u,
              g + (size_t)(rb + r) * KIN + k0 + c * 8);
    }
    CP_COMMIT();
}
__global__ __launch_bounds__(256) void k_gemm_in_m(const float* __restrict__ bias) {
    extern __shared__ __align__(128) char smraw[];
    uint32_t sb = smem_u32(smraw);
    const int tid = threadIdx.x, wid = tid >> 5, lane = tid & 31;
    const int row0 = blockIdx.y << 7, col0 = blockIdx.x << 7;
    const int wm = (wid >> 2) * 64, wn = (wid & 3) * 32;

    float acc[4][4][4];
    #pragma unroll
    for (int a = 0; a < 4; a++)
        #pragma unroll
        for (int b = 0; b < 4; b++)
            #pragma unroll
            for (int cdx = 0; cdx < 4; cdx++) acc[a][b][cdx] = 0.f;

    gin_load(sb, 0, 0, row0, col0, tid);
    for (int ck = 0; ck < 128; ck++) {
        int s = ck & 1;
        if (ck + 1 < 128) { gin_load(sb, s ^ 1, (ck + 1) * 32, row0, col0, tid); CP_WAIT(1); }
        else CP_WAIT(0);
        __syncthreads();
        uint32_t ab = sb + (uint32_t)s * 40960u, bb = ab + 20480u;
        #pragma unroll
        for (int half = 0; half < 2; half++) {
            uint32_t ah[4][4], al[4][4], bh[4][2], bl[4][2];
            #pragma unroll
            for (int mt = 0; mt < 4; mt++) {
                uint32_t ad = ab + (uint32_t)(wm + mt * 16 + (lane & 15)) * 80u
                                 + (uint32_t)(half * 2 + (lane >> 4)) * 16u;
                LDSM4(ah[mt], ad);
                LDSM4(al[mt], ad + 10240u);
            }
            #pragma unroll
            for (int ng = 0; ng < 2; ng++) {
                uint32_t bd = bb + (uint32_t)(wn + ng * 16 + (lane & 7) + ((lane & 16) ? 8 : 0)) * 80u
                                 + (uint32_t)(half * 2 + ((lane >> 3) & 1)) * 16u;
                uint32_t t4[4];
                LDSM4(t4, bd);
                bh[ng*2][0] = t4[0]; bh[ng*2][1] = t4[1]; bh[ng*2+1][0] = t4[2]; bh[ng*2+1][1] = t4[3];
                LDSM4(t4, bd + 10240u);
                bl[ng*2][0] = t4[0]; bl[ng*2][1] = t4[1]; bl[ng*2+1][0] = t4[2]; bl[ng*2+1][1] = t4[3];
            }
            #pragma unroll
            for (int mt = 0; mt < 4; mt++)
                #pragma unroll
                for (int nt = 0; nt < 4; nt++) {
                    MMA_BF16(acc[mt][nt], ah[mt], bh[nt]);
                    MMA_BF16(acc[mt][nt], ah[mt], bl[nt]);
                    MMA_BF16(acc[mt][nt], al[mt], bh[nt]);
                }
        }
        __syncthreads();
    }
    const int r0 = lane >> 2, cf = (lane & 3) * 2;
    #pragma unroll
    for (int mt = 0; mt < 4; mt++)
        #pragma unroll
        for (int i = 0; i < 2; i++) {
            int m = row0 + wm + mt * 16 + r0 + i * 8;
            if (m < BT) {
                #pragma unroll
                for (int nt = 0; nt < 4; nt++) {
                    int cg = col0 + wn + nt * 8 + cf;
                    float2 v;
                    v.x = acc[mt][nt][i*2+0] + bias[cg];
                    v.y = acc[mt][nt][i*2+1] + bias[cg+1];
                    size_t o = (size_t)m * KIN + cg;   // == linear index into [MROWS][64]
                    *(float2*)&d_h0[o] = v;
                    __nv_bfloat16 hx, lx, hy, ly;
                    bsplit(v.x, hx, lx); bsplit(v.y, hy, ly);
                    uint32_t uh = (uint32_t)__bfloat16_as_ushort(hx) | ((uint32_t)__bfloat16_as_ushort(hy) << 16);
                    uint32_t ul = (uint32_t)__bfloat16_as_ushort(lx) | ((uint32_t)__bfloat16_as_ushort(ly) << 16);
                    *(uint32_t*)&d_h0h[o] = uh;   // fixed p-term source
                    *(uint32_t*)&d_h0l[o] = ul;
                    *(uint32_t*)&d_hh[o]  = uh;   // current-h init
                    *(uint32_t*)&d_hl[o]  = ul;
                }
            }
        }
}

// ============ step GEMM: PRE = [h(t-1);h;h(t+1);h(n-1);h0](320) @ Wcat^T + gb2 + gst ============
// A sections read directly from h / h0 split arrays with row shifts + boundary zero-fill.
__device__ __forceinline__ void step_load(uint32_t sb, int st, int ck, int row0, int gg, int tid) {
    uint32_t base = sb + (uint32_t)st * 51200u;
    const int sec = ck >> 1;            // 0..4
    const int kin = (ck & 1) * 32;      // 0 or 32 within the 64-wide section
    #pragma unroll
    for (int w = 0; w < 10; w++) {
        int idx = tid + w * 256;        // 0..2559
        if (idx < 1024) {
            int t = idx >> 9, j = idx & 511, r = j >> 2, c = j & 3;
            int rr = row0 + r;
            int srow = rr;
            bool pred = true;
            if (sec == 0)      { pred = ((rr >> 6) % 63) != 0;  srow = rr - 64; }
            else if (sec == 2) { pred = ((rr >> 6) % 63) != 62; srow = rr + 64; }
            else if (sec == 3) { pred = (rr & 63) != 0;         srow = rr - 1; }
            if (!pred) srow = rr;       // keep address valid for zero-fill
            const __nv_bfloat16* g;
            if (sec == 4) g = t ? d_h0l : d_h0h;
            else          g = t ? d_hl  : d_hh;
            cpa16p(base + (uint32_t)t * 10240u + (uint32_t)r * 80u + (uint32_t)c * 16u,
                   g + (size_t)srow * 64 + kin + c * 8, pred);
        } else {
            int j2 = idx - 1024;        // 0..1535
            int t = j2 >= 768 ? 1 : 0;
            int j = j2 - t * 768, r = j >> 2, c = j & 3;
            const __nv_bfloat16* g = t ? d_wcl : d_wch;
            cpa16(base + 20480u + (uint32_t)t * 15360u + (uint32_t)r * 80u + (uint32_t)c * 16u,
                  g + (size_t)(gg * 192 + r) * KST + ck * 32 + c * 8);
        }
    }
    CP_COMMIT();
}
__global__ __launch_bounds__(256) void k_stepgemm_m() {
    extern __shared__ __align__(128) char smraw[];
    uint32_t sb = smem_u32(smraw);
    const int tid = threadIdx.x, wid = tid >> 5, lane = tid & 31;
    const int gg = blockIdx.x;                 // 0..2
    const int row0 = blockIdx.y << 7;          // 1008 tiles
    const int wm = (wid >> 2) * 64, wn = (wid & 3) * 48;

    float acc[4][6][4];
    #pragma unroll
    for (int a = 0; a < 4; a++)
        #pragma unroll
        for (int b = 0; b < 6; b++)
            #pragma unroll
            for (int cdx = 0; cdx < 4; cdx++) acc[a][b][cdx] = 0.f;

    step_load(sb, 0, 0, row0, gg, tid);
    for (int ck = 0; ck < 10; ck++) {
        int s = ck & 1;
        if (ck + 1 < 10) { step_load(sb, s ^ 1, ck + 1, row0, gg, tid); CP_WAIT(1); }
        else CP_WAIT(0);
        __syncthreads();
        uint32_t ab = sb + (uint32_t)s * 51200u, bb = ab + 20480u;
        #pragma unroll
        for (int half = 0; half < 2; half++) {
            uint32_t ah[4][4], al[4][4], bh[6][2], bl[6][2];
            #pragma unroll
            for (int mt = 0; mt < 4; mt++) {
                uint32_t ad = ab + (uint32_t)(wm + mt * 16 + (lane & 15)) * 80u
                                 + (uint32_t)(half * 2 + (lane >> 4)) * 16u;
                LDSM4(ah[mt], ad);
                LDSM4(al[mt], ad + 10240u);
            }
            #pragma unroll
            for (int ng = 0; ng < 3; ng++) {
                uint32_t bd = bb + (uint32_t)(wn + ng * 16 + (lane & 7) + ((lane & 16) ? 8 : 0)) * 80u
                                 + (uint32_t)(half * 2 + ((lane >> 3) & 1)) * 16u;
                uint32_t t4[4];
                LDSM4(t4, bd);
                bh[ng*2][0] = t4[0]; bh[ng*2][1] = t4[1]; bh[ng*2+1][0] = t4[2]; bh[ng*2+1][1] = t4[3];
                LDSM4(t4, bd + 15360u);
                bl[ng*2][0] = t4[0]; bl[ng*2][1] = t4[1]; bl[ng*2+1][0] = t4[2]; bl[ng*2+1][1] = t4[3];
            }
            #pragma unroll
            for (int mt = 0; mt < 4; mt++)
                #pragma unroll
                for (int nt = 0; nt < 6; nt++) {
                    MMA_BF16(acc[mt][nt], ah[mt], bh[nt]);
                    MMA_BF16(acc[mt][nt], ah[mt], bl[nt]);
                    MMA_BF16(acc[mt][nt], al[mt], bh[nt]);
                }
        }
        __syncthreads();
    }
    const int r0 = lane >> 2, cf = (lane & 3) * 2;
    #pragma unroll
    for (int mt = 0; mt < 4; mt++)
        #pragma unroll
        for (int i = 0; i < 2; i++) {
            int m = row0 + wm + mt * 16 + r0 + i * 8;
            int bone = m & 63, bt = m >> 6, b = bt / T_;
            #pragma unroll
            for (int nt = 0; nt < 6; nt++) {
                int nc = gg * 192 + wn + nt * 8 + cf;
                int g = nc >> 6, h = nc & 63;
                float2 a1 = *(const float2*)&d_gb2[(((size_t)g * 2048) + b * 64 + bone) * 64 + h];
                float2 a2 = *(const float2*)&d_gst[(((size_t)g * BT) + bt) * 64 + h];
                __half2 v = __floats2half2_rn(acc[mt][nt][i*2+0] + a1.x + a2.x,
                                              acc[mt][nt][i*2+1] + a1.y + a2.y);
                *(__half2*)&d_pre[(size_t)m * NCOLS + nc] = v;
            }
        }
}

// ---------- fused cell update (2 elems/thread, approx activations) + h split write ----------
__global__ void k_cell3(const float* __restrict__ c_old, float* __restrict__ c_new,
                        float* __restrict__ hout, int write_h) {
    int i2 = blockIdx.x * 256 + threadIdx.x;   // MROWS*32 pairs
    int hh = (i2 & 31) << 1;                   // 0,2,..,62
    int r = i2 >> 5;
    int n = r & 63, bt = r >> 6;
    int t = bt % T_, b = bt / T_;
    const __half* pb = d_pre + (size_t)r * NCOLS + hh;
    float2 i_n  = gate_sig(*(const __half2*)(pb + 0));
    float2 f_lt = gate_sig(*(const __half2*)(pb + 64));
    float2 f_ft = gate_sig(*(const __half2*)(pb + 128));
    float2 f_rt = gate_sig(*(const __half2*)(pb + 192));
    float2 f_s  = gate_sig(*(const __half2*)(pb + 256));
    float2 f_gt = gate_sig(*(const __half2*)(pb + 320));
    float2 f_gs = gate_sig(*(const __half2*)(pb + 384));
    float2 o_n  = gate_sig(*(const __half2*)(pb + 448));
    float2 c_nv = __half22float2(h2tanh_(*(const __half2*)(pb + 512)));
    int i = r * 64 + hh;
    float2 cc  = *(const float2*)&c_old[i];
    float2 ctb = make_float2(0.f, 0.f), cta = ctb, csb = ctb;
    if (t > 0)      ctb = *(const float2*)&c_old[i - 4096];
    if (t < T_ - 1) cta = *(const float2*)&c_old[i + 4096];
    if (n > 0)      csb = *(const float2*)&c_old[i - 64];
    float2 cgt = *(const float2*)&d_gt[(b * NB + n) * H_ + hh];
    float2 cgs = *(const float2*)&d_gs[bt * H_ + hh];
    float2 c;
    c.x = f_lt.x*ctb.x + f_ft.x*cc.x + f_rt.x*cta.x + f_s.x*csb.x
        + f_gt.x*cgt.x + f_gs.x*cgs.x + c_nv.x*i_n.x;
    c.y = f_lt.y*ctb.y + f_ft.y*cc.y + f_rt.y*cta.y + f_s.y*csb.y
        + f_gt.y*cgt.y + f_gs.y*cgs.y + c_nv.y*i_n.y;
    if (c_new) *(float2*)&c_new[i] = c;
    float2 hv;
    hv.x = o_n.x * ftanh_(c.x);
    hv.y = o_n.y * ftanh_(c.y);
    if (hout) *(float2*)&hout[i] = hv;
    if (write_h) {
        __nv_bfloat16 h0v, l0v, h1v, l1v;
        bsplit(hv.x, h0v, l0v); bsplit(hv.y, h1v, l1v);
        uint32_t uh = (uint32_t)__bfloat16_as_ushort(h0v) | ((uint32_t)__bfloat16_as_ushort(h1v) << 16);
        uint32_t ul = (uint32_t)__bfloat16_as_ushort(l0v) | ((uint32_t)__bfloat16_as_ushort(l1v) << 16);
        *(uint32_t*)&d_hh[i] = uh;
        *(uint32_t*)&d_hl[i] = ul;
    }
}

extern "C" void kernel_launch(void* const* d_in, const int* in_sizes, int n_in,
                              void* d_out, int out_size) {
    const float* enc = (const float*)d_in[0];
    const float* Win = (const float*)d_in[2];
    const float* bin = (const float*)d_in[3];
    const float* U   = (const float*)d_in[4];
    const float* Wt  = (const float*)d_in[5];
    const float* Ws  = (const float*)d_in[6];
    const float* Zt  = (const float*)d_in[7];
    const float* Zs  = (const float*)d_in[8];
    const float* bb  = (const float*)d_in[9];
    float* out = (float*)d_out;

    cudaFuncSetAttribute(k_gemm_in_m,  cudaFuncAttributeMaxDynamicSharedMemorySize, 81920);
    cudaFuncSetAttribute(k_stepgemm_m, cudaFuncAttributeMaxDynamicSharedMemorySize, 102400);

    void* c_sym = nullptr;
    cudaGetSymbolAddress(&c_sym, d_c);
    float* c0 = (float*)c_sym;
    float* c1 = c0 + (size_t)MROWS * H_;
    void* h0_sym = nullptr;
    cudaGetSymbolAddress(&h0_sym, d_h0);
    float* h0p = (float*)h0_sym;

    k_cvt_enc<<<(2048 * 1024) / 256, 256>>>(enc);
    k_trans_win<<<dim3(128, 128), dim3(32, 8)>>>(Win);
    k_wcat2<<<(NCOLS * KST + 255) / 256, 256>>>(Wt, Ws, U);
    k_gemm_in_m<<<dim3(32, 16), 256, 81920>>>(bin);
    k_mean_t<<<(B_ * NB * H_) / 256, 256>>>();
    k_mean_n<<<(BT * H_) / 256, 256>>>();
    k_ninegemm<<<dim3(NG, 32), 256>>>(0, Zt);
    k_ninegemm<<<dim3(NG, 32), 256>>>(1, Zs);
    k_gb2<<<(NG * 2048 * 64) / 256, 256>>>(bb);

    // step 0: c_old = h0, c_new = c0
    k_stepgemm_m<<<dim3(3, MROWS / 128), 256, 102400>>>();
    k_cell3<<<(MROWS * 32) / 256, 256>>>(h0p, c0, nullptr, 1);
    // step 1: c_old = c0, c_new = c1
    k_stepgemm_m<<<dim3(3, MROWS / 128), 256, 102400>>>();
    k_cell3<<<(MROWS * 32) / 256, 256>>>(c0, c1, nullptr, 1);
    // step 2: c_old = c1, no c_new, h -> out, no h write
    k_stepgemm_m<<<dim3(3, MROWS / 128), 256, 102400>>>();
    k_cell3<<<(MROWS * 32) / 256, 256>>>(c1, nullptr, out, 0);
}

// round 17
// speedup vs baseline: 1.0424x; 1.0052x over previous
#include <cuda_runtime.h>
#include <cuda_bf16.h>
#include <cuda_fp16.h>
#include <math.h>
#include <stdint.h>

#define B_ 32
#define T_ 63
#define NB 64
#define H_ 64
#define KIN 4096
#define BT (B_*T_)            // 2016
#define MROWS (BT*NB)         // 129024
#define NG 9
#define NCOLS (NG*H_)         // 576
#define KST 320               // [h(t-1); h; h(t+1); h(n-1); h0] x 64 (weights K)

__device__ float d_h0[MROWS*H_];                     // input projection output (fp32)
__device__ float d_c[2][MROWS*H_];                   // cell state ping-pong
__device__ __half d_pre[(size_t)MROWS*NCOLS];        // gate pre-activations (fp16)
__device__ float d_gt[B_*NB*H_];
__device__ float d_gs[BT*H_];
__device__ float d_gtt[NG*B_*NB*H_];
__device__ float d_gst[NG*BT*H_];
__device__ float d_gb2[NG*B_*NB*H_];                 // gtt + bias
__device__ __nv_bfloat16 d_Ah[2048*KIN], d_Al[2048*KIN];
__device__ __nv_bfloat16 d_Bh[(size_t)KIN*KIN], d_Bl[(size_t)KIN*KIN];   // Win^T [n][k]
__device__ __nv_bfloat16 d_h0h[MROWS*H_], d_h0l[MROWS*H_];               // h0 bf16 split (fixed)
__device__ __nv_bfloat16 d_hh[MROWS*H_],  d_hl[MROWS*H_];                // current h bf16 split
__device__ __nv_bfloat16 d_wch[NCOLS*KST], d_wcl[NCOLS*KST];             // [Wt;Ws;U]^T [n][k]

__constant__ int c_zs[NG] = {0,1,1,3,4,5,6,7,8};

// ---------- base-ISA async/mma helpers (NO tcgen05 — toolchain targets compute_103 base) ----------
__device__ __forceinline__ uint32_t smem_u32(const void* p) {
    uint32_t a;
    asm("{ .reg .u64 t; cvta.to.shared.u64 t, %1; cvt.u32.u64 %0, t; }" : "=r"(a) : "l"(p));
    return a;
}
__device__ __forceinline__ void cpa16(uint32_t dst, const void* src) {
    asm volatile("cp.async.cg.shared.global [%0], [%1], 16;" :: "r"(dst), "l"(src));
}
// predicated: pred=false -> zero-fill 16B (src-size 0)
__device__ __forceinline__ void cpa16p(uint32_t dst, const void* src, bool p) {
    int sz = p ? 16 : 0;
    asm volatile("cp.async.cg.shared.global [%0], [%1], 16, %2;" :: "r"(dst), "l"(src), "r"(sz));
}
#define CP_COMMIT() asm volatile("cp.async.commit_group;" ::: "memory")
#define CP_WAIT(n)  asm volatile("cp.async.wait_group %0;" :: "n"(n) : "memory")

#define LDSM4(r, a) \
    asm volatile("ldmatrix.sync.aligned.m8n8.x4.shared.b16 {%0,%1,%2,%3}, [%4];" \
        : "=r"((r)[0]), "=r"((r)[1]), "=r"((r)[2]), "=r"((r)[3]) : "r"(a))

#define MMA_BF16(d, a, b) \
    asm volatile("mma.sync.aligned.m16n8k16.row.col.f32.bf16.bf16.f32 " \
        "{%0,%1,%2,%3},{%4,%5,%6,%7},{%8,%9},{%0,%1,%2,%3};" \
        : "+f"((d)[0]), "+f"((d)[1]), "+f"((d)[2]), "+f"((d)[3]) \
        : "r"((a)[0]), "r"((a)[1]), "r"((a)[2]), "r"((a)[3]), "r"((b)[0]), "r"((b)[1]))

__device__ __forceinline__ void bsplit(float v, __nv_bfloat16& h, __nv_bfloat16& l) {
    h = __float2bfloat16(v);
    l = __float2bfloat16(v - __bfloat162float(h));
}
__device__ __forceinline__ void pack4(float4 v, uint2& uh, uint2& ul) {
    __nv_bfloat16 h0,h1,h2,h3,l0,l1,l2,l3;
    bsplit(v.x,h0,l0); bsplit(v.y,h1,l1); bsplit(v.z,h2,l2); bsplit(v.w,h3,l3);
    uh.x = (uint32_t)__bfloat16_as_ushort(h0) | ((uint32_t)__bfloat16_as_ushort(h1) << 16);
    uh.y = (uint32_t)__bfloat16_as_ushort(h2) | ((uint32_t)__bfloat16_as_ushort(h3) << 16);
    ul.x = (uint32_t)__bfloat16_as_ushort(l0) | ((uint32_t)__bfloat16_as_ushort(l1) << 16);
    ul.y = (uint32_t)__bfloat16_as_ushort(l2) | ((uint32_t)__bfloat16_as_ushort(l3) << 16);
}

// fast activation helpers (h2tanh name collides with cuda_fp16.hpp builtin)
__device__ __forceinline__ __half2 h2tanh_(__half2 x) {
    uint32_t xi = *(uint32_t*)&x, yo;
    asm("tanh.approx.f16x2 %0, %1;" : "=r"(yo) : "r"(xi));
    return *(__half2*)&yo;
}
__device__ __forceinline__ float ftanh_(float x) {
    float y;
    asm("tanh.approx.f32 %0, %1;" : "=f"(y) : "f"(x));
    return y;
}
// sigma(x) = 0.5*tanh(0.5x)+0.5, two lanes at once (approx)
__device__ __forceinline__ float2 gate_sig(__half2 x) {
    const __half2 h5 = __float2half2_rn(0.5f);
    __half2 g = __hfma2(h2tanh_(__hmul2(x, h5)), h5, h5);
    return __half22float2(g);
}

// ---------- prep kernels ----------
__global__ void k_cvt_enc(const float* __restrict__ A) {
    int i = blockIdx.x * 256 + threadIdx.x;          // 2048*1024 quads
    if (i >= 2048 * 1024) return;
    int r = i >> 10, c4 = (i & 1023) << 2;
    float4 v = make_float4(0.f,0.f,0.f,0.f);
    if (r < BT) v = *(const float4*)&A[(size_t)r * KIN + c4];
    uint2 uh, ul; pack4(v, uh, ul);
    size_t o = (size_t)r * KIN + c4;
    *(uint2*)&d_Ah[o] = uh; *(uint2*)&d_Al[o] = ul;
}
__global__ void k_trans_win(const float* __restrict__ W) {
    __shared__ float t[32][33];
    int n0 = blockIdx.x * 32, k0 = blockIdx.y * 32;
    int tx = threadIdx.x, ty = threadIdx.y;  // (32,8)
    #pragma unroll
    for (int j = 0; j < 32; j += 8)
        t[ty + j][tx] = W[(size_t)(k0 + ty + j) * KIN + n0 + tx];
    __syncthreads();
    #pragma unroll
    for (int j = 0; j < 32; j += 8) {
        float v = t[tx][ty + j];
        size_t o = (size_t)(n0 + ty + j) * KIN + k0 + tx;
        __nv_bfloat16 h, l; bsplit(v, h, l);
        d_Bh[o] = h; d_Bl[o] = l;
    }
}
// build [Wt;Ws;U]^T [576 x 320]
__global__ void k_wcat2(const float* __restrict__ Wt, const float* __restrict__ Ws,
                        const float* __restrict__ U) {
    int i = blockIdx.x * 256 + threadIdx.x;   // 576*320
    if (i >= NCOLS * KST) return;
    int n = i / KST, k = i % KST;
    int g = n >> 6, h = n & 63;
    float v = (k < 192) ? Wt[(g * 192 + k) * 64 + h]
            : (k < 256) ? Ws[(g * 64 + (k - 192)) * 64 + h]
                        : U [(g * 64 + (k - 256)) * 64 + h];
    __nv_bfloat16 hh, ll; bsplit(v, hh, ll);
    d_wch[i] = hh; d_wcl[i] = ll;
}
__global__ void k_gb2(const float* __restrict__ bb) {
    int i = blockIdx.x * 256 + threadIdx.x;
    if (i >= NG * 2048 * 64) return;
    int h = i & 63, m = (i >> 6) & 2047, g = i >> 17;
    d_gb2[i] = d_gtt[i] + bb[(size_t)g * 4096 + (m & 63) * 64 + h];
}

// ---------- means / small gemms ----------
__global__ void k_mean_t() {
    int i = blockIdx.x * 256 + threadIdx.x;
    int hh = i & 63, n = (i >> 6) & 63, b = i >> 12;
    const float* p = d_h0 + ((size_t)(b * T_) * NB + n) * H_ + hh;
    float s = 0.f;
    for (int t = 0; t < T_; t++) s += p[(size_t)t * NB * H_];
    d_gt[i] = s * (1.0f / T_);
}
__global__ void k_mean_n() {
    int i = blockIdx.x * 256 + threadIdx.x;
    int hh = i & 63, bt = i >> 6;
    const float* p = d_h0 + (size_t)bt * NB * H_ + hh;
    float s = 0.f;
    for (int n = 0; n < NB; n++) s += p[n * H_];
    d_gs[i] = s * (1.0f / NB);
}
__global__ __launch_bounds__(256) void k_ninegemm(int which, const float* __restrict__ Wbase) {
    const int g = blockIdx.x;
    const int m0 = blockIdx.y * 64;
    const float* X = which ? d_gs : d_gt;
    float* out = which ? d_gst : d_gtt;
    const int M = which ? BT : (B_ * NB);
    const float* Wg = Wbase + (size_t)(which ? c_zs[g] : g) * 4096;
    __shared__ float XT[64][68];
    __shared__ float Wsm[64][68];
    const int tid = threadIdx.x;
    for (int i = tid; i < 4096; i += 256) {
        int r = i >> 6, k = i & 63;
        XT[k][r] = (m0 + r < M) ? X[(size_t)(m0 + r) * 64 + k] : 0.f;
        Wsm[r][k] = Wg[i];
    }
    __syncthreads();
    const int tx = tid & 15, ty = tid >> 4;
    float acc[4][4];
    #pragma unroll
    for (int i = 0; i < 4; i++)
        #pragma unroll
        for (int j = 0; j < 4; j++) acc[i][j] = 0.f;
    #pragma unroll 16
    for (int kk = 0; kk < 64; kk++) {
        float4 a = *(const float4*)&XT[kk][ty * 4];
        float4 w = *(const float4*)&Wsm[kk][tx * 4];
        float av[4] = {a.x,a.y,a.z,a.w}, wv[4] = {w.x,w.y,w.z,w.w};
        #pragma unroll
        for (int i = 0; i < 4; i++)
            #pragma unroll
            for (int j = 0; j < 4; j++) acc[i][j] = fmaf(av[i], wv[j], acc[i][j]);
    }
    #pragma unroll
    for (int i = 0; i < 4; i++) {
        int row = m0 + ty * 4 + i;
        if (row >= M) break;
        float4 v = make_float4(acc[i][0], acc[i][1], acc[i][2], acc[i][3]);
        *(float4*)&out[((size_t)g * M + row) * 64 + tx * 4] = v;
    }
}

// ============ mma.sync input GEMM: h0 = enc @ Win + bias (2-stage, 2 CTAs/SM) ============
__device__ __forceinline__ void gin_load(uint32_t sb, int st, int k0, int row0, int col0, int tid) {
    uint32_t base = sb + (uint32_t)st * 40960u;
    #pragma unroll
    for (int w = 0; w < 8; w++) {
        int idx = tid + w * 256;        // 0..2047
        int t = idx >> 9;               // 0:Ah 1:Al 2:Bh 3:Bl
        int j = idx & 511;
        int r = j >> 2, c = j & 3;
        const __nv_bfloat16* g;
        int rb;
        if (t == 0)      { g = d_Ah; rb = row0; }
        else if (t == 1) { g = d_Al; rb = row0; }
        else if (t == 2) { g = d_Bh; rb = col0; }
        else             { g = d_Bl; rb = col0; }
        cpa16(base + (uint32_t)t * 10240u + (uint32_t)r * 80u + (uint32_t)c * 16u,
              g + (size_t)(rb + r) * KIN + k0 + c * 8);
    }
    CP_COMMIT();
}
__global__ __launch_bounds__(256) void k_gemm_in_m(const float* __restrict__ bias) {
    extern __shared__ __align__(128) char smraw[];
    uint32_t sb = smem_u32(smraw);
    const int tid = threadIdx.x, wid = tid >> 5, lane = tid & 31;
    const int row0 = blockIdx.y << 7, col0 = blockIdx.x << 7;
    const int wm = (wid >> 2) * 64, wn = (wid & 3) * 32;

    float acc[4][4][4];
    #pragma unroll
    for (int a = 0; a < 4; a++)
        #pragma unroll
        for (int b = 0; b < 4; b++)
            #pragma unroll
            for (int cdx = 0; cdx < 4; cdx++) acc[a][b][cdx] = 0.f;

    gin_load(sb, 0, 0, row0, col0, tid);
    for (int ck = 0; ck < 128; ck++) {
        int s = ck & 1;
        if (ck + 1 < 128) { gin_load(sb, s ^ 1, (ck + 1) * 32, row0, col0, tid); CP_WAIT(1); }
        else CP_WAIT(0);
        __syncthreads();
        uint32_t ab = sb + (uint32_t)s * 40960u, bb = ab + 20480u;
        #pragma unroll
        for (int half = 0; half < 2; half++) {
            uint32_t ah[4][4], al[4][4], bh[4][2], bl[4][2];
            #pragma unroll
            for (int mt = 0; mt < 4; mt++) {
                uint32_t ad = ab + (uint32_t)(wm + mt * 16 + (lane & 15)) * 80u
                                 + (uint32_t)(half * 2 + (lane >> 4)) * 16u;
                LDSM4(ah[mt], ad);
                LDSM4(al[mt], ad + 10240u);
            }
            #pragma unroll
            for (int ng = 0; ng < 2; ng++) {
                uint32_t bd = bb + (uint32_t)(wn + ng * 16 + (lane & 7) + ((lane & 16) ? 8 : 0)) * 80u
                                 + (uint32_t)(half * 2 + ((lane >> 3) & 1)) * 16u;
                uint32_t t4[4];
                LDSM4(t4, bd);
                bh[ng*2][0] = t4[0]; bh[ng*2][1] = t4[1]; bh[ng*2+1][0] = t4[2]; bh[ng*2+1][1] = t4[3];
                LDSM4(t4, bd + 10240u);
                bl[ng*2][0] = t4[0]; bl[ng*2][1] = t4[1]; bl[ng*2+1][0] = t4[2]; bl[ng*2+1][1] = t4[3];
            }
            // product loop hoisted OUTER: consecutive MMAs hit different accumulators
            // (per-acc order stays bh -> bl -> lh, so numerics are bit-identical)
            #pragma unroll
            for (int mt = 0; mt < 4; mt++)
                #pragma unroll
                for (int nt = 0; nt < 4; nt++)
                    MMA_BF16(acc[mt][nt], ah[mt], bh[nt]);
            #pragma unroll
            for (int mt = 0; mt < 4; mt++)
                #pragma unroll
                for (int nt = 0; nt < 4; nt++)
                    MMA_BF16(acc[mt][nt], ah[mt], bl[nt]);
            #pragma unroll
            for (int mt = 0; mt < 4; mt++)
                #pragma unroll
                for (int nt = 0; nt < 4; nt++)
                    MMA_BF16(acc[mt][nt], al[mt], bh[nt]);
        }
        __syncthreads();
    }
    const int r0 = lane >> 2, cf = (lane & 3) * 2;
    #pragma unroll
    for (int mt = 0; mt < 4; mt++)
        #pragma unroll
        for (int i = 0; i < 2; i++) {
            int m = row0 + wm + mt * 16 + r0 + i * 8;
            if (m < BT) {
                #pragma unroll
                for (int nt = 0; nt < 4; nt++) {
                    int cg = col0 + wn + nt * 8 + cf;
                    float2 v;
                    v.x = acc[mt][nt][i*2+0] + bias[cg];
                    v.y = acc[mt][nt][i*2+1] + bias[cg+1];
                    size_t o = (size_t)m * KIN + cg;   // == linear index into [MROWS][64]
                    *(float2*)&d_h0[o] = v;
                    __nv_bfloat16 hx, lx, hy, ly;
                    bsplit(v.x, hx, lx); bsplit(v.y, hy, ly);
                    uint32_t uh = (uint32_t)__bfloat16_as_ushort(hx) | ((uint32_t)__bfloat16_as_ushort(hy) << 16);
                    uint32_t ul = (uint32_t)__bfloat16_as_ushort(lx) | ((uint32_t)__bfloat16_as_ushort(ly) << 16);
                    *(uint32_t*)&d_h0h[o] = uh;   // fixed p-term source
                    *(uint32_t*)&d_h0l[o] = ul;
                    *(uint32_t*)&d_hh[o]  = uh;   // current-h init
                    *(uint32_t*)&d_hl[o]  = ul;
                }
            }
        }
}

// ============ step GEMM: PRE = [h(t-1);h;h(t+1);h(n-1);h0](320) @ Wcat^T + gb2 + gst ============
// A sections read directly from h / h0 split arrays with row shifts + boundary zero-fill.
__device__ __forceinline__ void step_load(uint32_t sb, int st, int ck, int row0, int gg, int tid) {
    uint32_t base = sb + (uint32_t)st * 51200u;
    const int sec = ck >> 1;            // 0..4
    const int kin = (ck & 1) * 32;      // 0 or 32 within the 64-wide section
    // hoisted boundary predicates: tile covers exactly 2 bt values
    const int t0 = (row0 >> 6) % T_;
    const int t1 = (t0 + 1 == T_) ? 0 : t0 + 1;
    #pragma unroll
    for (int w = 0; w < 10; w++) {
        int idx = tid + w * 256;        // 0..2559
        if (idx < 1024) {
            int t = idx >> 9, j = idx & 511, r = j >> 2, c = j & 3;
            int rr = row0 + r;
            int tt = (r < 64) ? t0 : t1;
            int srow = rr;
            bool pred = true;
            if (sec == 0)      { pred = tt != 0;        srow = rr - 64; }
            else if (sec == 2) { pred = tt != T_ - 1;   srow = rr + 64; }
            else if (sec == 3) { pred = (r & 63) != 0;  srow = rr - 1; }
            if (!pred) srow = rr;       // keep address valid for zero-fill
            const __nv_bfloat16* g;
            if (sec == 4) g = t ? d_h0l : d_h0h;
            else          g = t ? d_hl  : d_hh;
            cpa16p(base + (uint32_t)t * 10240u + (uint32_t)r * 80u + (uint32_t)c * 16u,
                   g + (size_t)srow * 64 + kin + c * 8, pred);
        } else {
            int j2 = idx - 1024;        // 0..1535
            int t = j2 >= 768 ? 1 : 0;
            int j = j2 - t * 768, r = j >> 2, c = j & 3;
            const __nv_bfloat16* g = t ? d_wcl : d_wch;
            cpa16(base + 20480u + (uint32_t)t * 15360u + (uint32_t)r * 80u + (uint32_t)c * 16u,
                  g + (size_t)(gg * 192 + r) * KST + ck * 32 + c * 8);
        }
    }
    CP_COMMIT();
}
__global__ __launch_bounds__(256) void k_stepgemm_m() {
    extern __shared__ __align__(128) char smraw[];
    uint32_t sb = smem_u32(smraw);
    const int tid = threadIdx.x, wid = tid >> 5, lane = tid & 31;
    const int gg = blockIdx.x;                 // 0..2
    const int row0 = blockIdx.y << 7;          // 1008 tiles
    const int wm = (wid >> 2) * 64, wn = (wid & 3) * 48;

    float acc[4][6][4];
    #pragma unroll
    for (int a = 0; a < 4; a++)
        #pragma unroll
        for (int b = 0; b < 6; b++)
            #pragma unroll
            for (int cdx = 0; cdx < 4; cdx++) acc[a][b][cdx] = 0.f;

    step_load(sb, 0, 0, row0, gg, tid);
    for (int ck = 0; ck < 10; ck++) {
        int s = ck & 1;
        if (ck + 1 < 10) { step_load(sb, s ^ 1, ck + 1, row0, gg, tid); CP_WAIT(1); }
        else CP_WAIT(0);
        __syncthreads();
        uint32_t ab = sb + (uint32_t)s * 51200u, bb = ab + 20480u;
        #pragma unroll
        for (int half = 0; half < 2; half++) {
            uint32_t ah[4][4], al[4][4], bh[6][2], bl[6][2];
            #pragma unroll
            for (int mt = 0; mt < 4; mt++) {
                uint32_t ad = ab + (uint32_t)(wm + mt * 16 + (lane & 15)) * 80u
                                 + (uint32_t)(half * 2 + (lane >> 4)) * 16u;
                LDSM4(ah[mt], ad);
                LDSM4(al[mt], ad + 10240u);
            }
            #pragma unroll
            for (int ng = 0; ng < 3; ng++) {
                uint32_t bd = bb + (uint32_t)(wn + ng * 16 + (lane & 7) + ((lane & 16) ? 8 : 0)) * 80u
                                 + (uint32_t)(half * 2 + ((lane >> 3) & 1)) * 16u;
                uint32_t t4[4];
                LDSM4(t4, bd);
                bh[ng*2][0] = t4[0]; bh[ng*2][1] = t4[1]; bh[ng*2+1][0] = t4[2]; bh[ng*2+1][1] = t4[3];
                LDSM4(t4, bd + 15360u);
                bl[ng*2][0] = t4[0]; bl[ng*2][1] = t4[1]; bl[ng*2+1][0] = t4[2]; bl[ng*2+1][1] = t4[3];
            }
            // product loop hoisted OUTER (bit-identical per-acc order)
            #pragma unroll
            for (int mt = 0; mt < 4; mt++)
                #pragma unroll
                for (int nt = 0; nt < 6; nt++)
                    MMA_BF16(acc[mt][nt], ah[mt], bh[nt]);
            #pragma unroll
            for (int mt = 0; mt < 4; mt++)
                #pragma unroll
                for (int nt = 0; nt < 6; nt++)
                    MMA_BF16(acc[mt][nt], ah[mt], bl[nt]);
            #pragma unroll
            for (int mt = 0; mt < 4; mt++)
                #pragma unroll
                for (int nt = 0; nt < 6; nt++)
                    MMA_BF16(acc[mt][nt], al[mt], bh[nt]);
        }
        __syncthreads();
    }
    const int r0 = lane >> 2, cf = (lane & 3) * 2;
    #pragma unroll
    for (int mt = 0; mt < 4; mt++)
        #pragma unroll
        for (int i = 0; i < 2; i++) {
            int m = row0 + wm + mt * 16 + r0 + i * 8;
            int bone = m & 63, bt = m >> 6, b = bt / T_;
            #pragma unroll
            for (int nt = 0; nt < 6; nt++) {
                int nc = gg * 192 + wn + nt * 8 + cf;
                int g = nc >> 6, h = nc & 63;
                float2 a1 = *(const float2*)&d_gb2[(((size_t)g * 2048) + b * 64 + bone) * 64 + h];
                float2 a2 = *(const float2*)&d_gst[(((size_t)g * BT) + bt) * 64 + h];
                __half2 v = __floats2half2_rn(acc[mt][nt][i*2+0] + a1.x + a2.x,
                                              acc[mt][nt][i*2+1] + a1.y + a2.y);
                *(__half2*)&d_pre[(size_t)m * NCOLS + nc] = v;
            }
        }
}

// ---------- fused cell update (2 elems/thread, approx activations) + h split write ----------
__global__ void k_cell3(const float* __restrict__ c_old, float* __restrict__ c_new,
                        float* __restrict__ hout, int write_h) {
    int i2 = blockIdx.x * 256 + threadIdx.x;   // MROWS*32 pairs
    int hh = (i2 & 31) << 1;                   // 0,2,..,62
    int r = i2 >> 5;
    int n = r & 63, bt = r >> 6;
    int t = bt % T_, b = bt / T_;
    const __half* pb = d_pre + (size_t)r * NCOLS + hh;
    float2 i_n  = gate_sig(*(const __half2*)(pb + 0));
    float2 f_lt = gate_sig(*(const __half2*)(pb + 64));
    float2 f_ft = gate_sig(*(const __half2*)(pb + 128));
    float2 f_rt = gate_sig(*(const __half2*)(pb + 192));
    float2 f_s  = gate_sig(*(const __half2*)(pb + 256));
    float2 f_gt = gate_sig(*(const __half2*)(pb + 320));
    float2 f_gs = gate_sig(*(const __half2*)(pb + 384));
    float2 o_n  = gate_sig(*(const __half2*)(pb + 448));
    float2 c_nv = __half22float2(h2tanh_(*(const __half2*)(pb + 512)));
    int i = r * 64 + hh;
    float2 cc  = *(const float2*)&c_old[i];
    float2 ctb = make_float2(0.f, 0.f), cta = ctb, csb = ctb;
    if (t > 0)      ctb = *(const float2*)&c_old[i - 4096];
    if (t < T_ - 1) cta = *(const float2*)&c_old[i + 4096];
    if (n > 0)      csb = *(const float2*)&c_old[i - 64];
    float2 cgt = *(const float2*)&d_gt[(b * NB + n) * H_ + hh];
    float2 cgs = *(const float2*)&d_gs[bt * H_ + hh];
    float2 c;
    c.x = f_lt.x*ctb.x + f_ft.x*cc.x + f_rt.x*cta.x + f_s.x*csb.x
        + f_gt.x*cgt.x + f_gs.x*cgs.x + c_nv.x*i_n.x;
    c.y = f_lt.y*ctb.y + f_ft.y*cc.y + f_rt.y*cta.y + f_s.y*csb.y
        + f_gt.y*cgt.y + f_gs.y*cgs.y + c_nv.y*i_n.y;
    if (c_new) *(float2*)&c_new[i] = c;
    float2 hv;
    hv.x = o_n.x * ftanh_(c.x);
    hv.y = o_n.y * ftanh_(c.y);
    if (hout) *(float2*)&hout[i] = hv;
    if (write_h) {
        __nv_bfloat16 h0v, l0v, h1v, l1v;
        bsplit(hv.x, h0v, l0v); bsplit(hv.y, h1v, l1v);
        uint32_t uh = (uint32_t)__bfloat16_as_ushort(h0v) | ((uint32_t)__bfloat16_as_ushort(h1v) << 16);
        uint32_t ul = (uint32_t)__bfloat16_as_ushort(l0v) | ((uint32_t)__bfloat16_as_ushort(l1v) << 16);
        *(uint32_t*)&d_hh[i] = uh;
        *(uint32_t*)&d_hl[i] = ul;
    }
}

extern "C" void kernel_launch(void* const* d_in, const int* in_sizes, int n_in,
                              void* d_out, int out_size) {
    const float* enc = (const float*)d_in[0];
    const float* Win = (const float*)d_in[2];
    const float* bin = (const float*)d_in[3];
    const float* U   = (const float*)d_in[4];
    const float* Wt  = (const float*)d_in[5];
    const float* Ws  = (const float*)d_in[6];
    const float* Zt  = (const float*)d_in[7];
    const float* Zs  = (const float*)d_in[8];
    const float* bb  = (const float*)d_in[9];
    float* out = (float*)d_out;

    cudaFuncSetAttribute(k_gemm_in_m,  cudaFuncAttributeMaxDynamicSharedMemorySize, 81920);
    cudaFuncSetAttribute(k_stepgemm_m, cudaFuncAttributeMaxDynamicSharedMemorySize, 102400);

    void* c_sym = nullptr;
    cudaGetSymbolAddress(&c_sym, d_c);
    float* c0 = (float*)c_sym;
    float* c1 = c0 + (size_t)MROWS * H_;
    void* h0_sym = nullptr;
    cudaGetSymbolAddress(&h0_sym, d_h0);
    float* h0p = (float*)h0_sym;

    k_cvt_enc<<<(2048 * 1024) / 256, 256>>>(enc);
    k_trans_win<<<dim3(128, 128), dim3(32, 8)>>>(Win);
    k_wcat2<<<(NCOLS * KST + 255) / 256, 256>>>(Wt, Ws, U);
    k_gemm_in_m<<<dim3(32, 16), 256, 81920>>>(bin);
    k_mean_t<<<(B_ * NB * H_) / 256, 256>>>();
    k_mean_n<<<(BT * H_) / 256, 256>>>();
    k_ninegemm<<<dim3(NG, 32), 256>>>(0, Zt);
    k_ninegemm<<<dim3(NG, 32), 256>>>(1, Zs);
    k_gb2<<<(NG * 2048 * 64) / 256, 256>>>(bb);

    // step 0: c_old = h0, c_new = c0
    k_stepgemm_m<<<dim3(3, MROWS / 128), 256, 102400>>>();
    k_cell3<<<(MROWS * 32) / 256, 256>>>(h0p, c0, nullptr, 1);
    // step 1: c_old = c0, c_new = c1
    k_stepgemm_m<<<dim3(3, MROWS / 128), 256, 102400>>>();
    k_cell3<<<(MROWS * 32) / 256, 256>>>(c0, c1, nullptr, 1);
    // step 2: c_old = c1, no c_new, h -> out, no h write
    k_stepgemm_m<<<dim3(3, MROWS / 128), 256, 102400>>>();
    k_cell3<<<(MROWS * 32) / 256, 256>>>(c1, nullptr, out, 0);
}